// round 9
// baseline (speedup 1.0000x reference)
#include <cuda_runtime.h>
#include <cuda_bf16.h>
#include <cstdint>

#define NB 256
#define IN_F 1024
#define B_EXTRA 256
#define KDIM 16
#define OUT_F 1280
#define JDIM 4096            // B_EXTRA * KDIM

// ---------------- device scratch ----------------
__device__ float g_M[NB * JDIM];   // 4 MB

// ---------------- helpers ----------------
__device__ __forceinline__ uint32_t smem_u32(const void* p) {
    uint32_t a;
    asm("{ .reg .u64 t; cvta.to.shared.u64 t, %1; cvt.u32.u64 %0, t; }" : "=r"(a) : "l"(p));
    return a;
}
#define SWZ(x) ((x) ^ (((x) >> 3) & 0x70))

__device__ __forceinline__ void cp16(uint32_t dst, const void* src) {
    asm volatile("cp.async.cg.shared.global [%0], [%1], 16;" :: "r"(dst), "l"(src) : "memory");
}
#define CP_COMMIT() asm volatile("cp.async.commit_group;" ::: "memory")
#define CP_WAITG1() asm volatile("cp.async.wait_group 1;" ::: "memory")
#define CP_WAITG0() asm volatile("cp.async.wait_group 0;" ::: "memory")

__device__ __forceinline__ void ldsm_x4(uint32_t* r, uint32_t a) {
    asm volatile("ldmatrix.sync.aligned.m8n8.x4.shared.b16 {%0,%1,%2,%3}, [%4];"
        : "=r"(r[0]), "=r"(r[1]), "=r"(r[2]), "=r"(r[3]) : "r"(a));
}
__device__ __forceinline__ void ldsm_x4_t(uint32_t* r, uint32_t a) {
    asm volatile("ldmatrix.sync.aligned.m8n8.x4.trans.shared.b16 {%0,%1,%2,%3}, [%4];"
        : "=r"(r[0]), "=r"(r[1]), "=r"(r[2]), "=r"(r[3]) : "r"(a));
}
__device__ __forceinline__ void mma_16816(float* d, const uint32_t* a, const uint32_t* b) {
    asm volatile("mma.sync.aligned.m16n8k16.row.col.f32.bf16.bf16.f32 "
        "{%0,%1,%2,%3}, {%4,%5,%6,%7}, {%8,%9}, {%0,%1,%2,%3};"
        : "+f"(d[0]), "+f"(d[1]), "+f"(d[2]), "+f"(d[3])
        : "r"(a[0]), "r"(a[1]), "r"(a[2]), "r"(a[3]), "r"(b[0]), "r"(b[1]));
}
__device__ __forceinline__ uint32_t cvt_bf16x2(float flo, float fhi) {
    uint32_t d;
    asm("cvt.rn.bf16x2.f32 %0, %1, %2;" : "=r"(d) : "f"(fhi), "f"(flo));
    return d;
}
__device__ __forceinline__ int vad4add(uint32_t a, uint32_t b, int c) {
    int d;
    asm("vabsdiff4.u32.s32.s32.add %0, %1, %2, %3;" : "=r"(d) : "r"(a), "r"(b), "r"(c));
    return d;
}
__device__ __forceinline__ float ex2f(float v) {
    float y;
    asm("ex2.approx.f32 %0, %1;" : "=f"(y) : "f"(v));
    return y;
}

// ---------------------------------------------------------------------------
// Kernel 1: fused GEMM — fp32 inputs cp.async'd to padded smem staging,
// converted to bf16 smem by the SAME threads (no extra barrier), HMMA mainloop.
// CTA 128x64, BK=64, 16 k-tiles, 8 warps. Grid (64, 2) = 128 CTAs.
// ---------------------------------------------------------------------------
#define BM 128
#define BN 64
#define BK 64
#define NT_K 16

// smem layout (bytes, 1024-aligned sections)
#define A16_OFF(s) ((s) * 16384)                 // 2 x 16 KB  bf16 A tiles
#define B16_OFF(s) (32768 + (s) * 8192)          // 2 x  8 KB  bf16 B tiles
#define S32A_OFF(s) (49152 + (s) * 34816)        // 2 x 34 KB  fp32 A staging (68f rows)
#define S32B_OFF(s) (118784 + (s) * 17408)       // 2 x 17 KB  fp32 B staging (68f rows)
#define GEMM_SMEM 153600
#define SROW 272                                  // 68 floats padded row stride

__global__ __launch_bounds__(256) void gemm_kernel(const float* __restrict__ x,
                                                   const float* __restrict__ W) {
    extern __shared__ __align__(1024) char smem[];
    const uint32_t sbase = smem_u32(smem);
    const int tid = threadIdx.x;
    const int wid = tid >> 5;
    const int lane = tid & 31;
    const int m0 = blockIdx.y * BM;
    const int n0 = blockIdx.x * BN;
    const int wm = (wid >> 1) * 32;
    const int wn = (wid & 1) * 32;

    // cp.async: A 2048 chunks (8/thr), B 1024 chunks (4/thr); chunk = 16B = 4 fp32
    auto issue_tile = [&](int t) {
        const int s = t & 1;
        const int kk = t * BK;
        const uint32_t SA = sbase + S32A_OFF(s);
        const uint32_t SB = sbase + S32B_OFF(s);
#pragma unroll
        for (int q = 0; q < 8; q++) {
            const int i = tid + q * 256;
            const int r = i >> 4, c = i & 15;
            cp16(SA + r * SROW + c * 16, x + (size_t)(m0 + r) * IN_F + kk + c * 4);
        }
#pragma unroll
        for (int q = 0; q < 4; q++) {
            const int i = tid + q * 256;
            const int r = i >> 4, c = i & 15;
            cp16(SB + r * SROW + c * 16, W + (size_t)(kk + r) * JDIM + n0 + c * 4);
        }
        CP_COMMIT();
    };
    // convert own chunks: S32[s] (fp32) -> A16[s]/B16[s] (bf16, SW128)
    auto convert_tile = [&](int t) {
        const int s = t & 1;
        const uint32_t SA = sbase + S32A_OFF(s);
        const uint32_t SB = sbase + S32B_OFF(s);
        char* A = smem + A16_OFF(s);
        char* B = smem + B16_OFF(s);
#pragma unroll
        for (int q = 0; q < 8; q++) {
            const int i = tid + q * 256;
            const int r = i >> 4, c = i & 15;
            float4 v;
            asm volatile("ld.shared.v4.f32 {%0,%1,%2,%3}, [%4];"
                : "=f"(v.x), "=f"(v.y), "=f"(v.z), "=f"(v.w) : "r"(SA + r * SROW + c * 16));
            *(uint2*)(A + SWZ(r * 128 + c * 8)) =
                make_uint2(cvt_bf16x2(v.x, v.y), cvt_bf16x2(v.z, v.w));
        }
#pragma unroll
        for (int q = 0; q < 4; q++) {
            const int i = tid + q * 256;
            const int r = i >> 4, c = i & 15;
            float4 v;
            asm volatile("ld.shared.v4.f32 {%0,%1,%2,%3}, [%4];"
                : "=f"(v.x), "=f"(v.y), "=f"(v.z), "=f"(v.w) : "r"(SB + r * SROW + c * 16));
            *(uint2*)(B + SWZ(r * 128 + c * 8)) =
                make_uint2(cvt_bf16x2(v.x, v.y), cvt_bf16x2(v.z, v.w));
        }
    };

    float acc[2][4][4] = {};

    // prologue
    issue_tile(0);
    issue_tile(1);
    CP_WAITG1();          // group 0 landed
    convert_tile(0);      // own-thread data: no barrier needed before
    __syncthreads();      // publish A16[0]/B16[0]

    for (int t = 0; t < NT_K; t++) {
        // S32[t&1] fully converted by all threads (guarded by last sync) -> reuse
        if (t + 2 < NT_K) issue_tile(t + 2);

        const uint32_t Ab = sbase + A16_OFF(t & 1);
        const uint32_t Bb = sbase + B16_OFF(t & 1);
#pragma unroll
        for (int st = 0; st < 4; st++) {
            uint32_t af[2][4], bf[2][4];
#pragma unroll
            for (int mt = 0; mt < 2; mt++)
                ldsm_x4(af[mt], Ab + SWZ((wm + mt * 16 + (lane & 15)) * 128 +
                                         st * 32 + (lane >> 4) * 16));
#pragma unroll
            for (int nt = 0; nt < 2; nt++)
                ldsm_x4_t(bf[nt], Bb + SWZ((st * 16 + (lane & 15)) * 128 +
                                           (wn + nt * 16) * 2 + (lane >> 4) * 16));
#pragma unroll
            for (int mt = 0; mt < 2; mt++)
#pragma unroll
                for (int j = 0; j < 4; j++)
                    mma_16816(acc[mt][j], af[mt], bf[j >> 1] + (j & 1) * 2);
        }

        if (t + 1 < NT_K) {
            // group t+1 must be fully landed (t+2 may still be in flight)
            if (t + 2 < NT_K) CP_WAITG1(); else CP_WAITG0();
            convert_tile(t + 1);   // own chunks only; writes A16/B16[(t+1)&1],
                                   // last read by MMA(t-1) (done at prior sync)
            __syncthreads();       // publish converts; all warps done with MMA(t)
        }
    }

    // epilogue: write fp32 tiles to g_M
    const int g = lane >> 2, tig = lane & 3;
#pragma unroll
    for (int mt = 0; mt < 2; mt++)
#pragma unroll
        for (int j = 0; j < 4; j++) {
            const size_t base = (size_t)(m0 + wm + mt * 16 + g) * JDIM +
                                n0 + wn + j * 8 + tig * 2;
            *(float2*)(g_M + base)            = make_float2(acc[mt][j][0], acc[mt][j][1]);
            *(float2*)(g_M + base + 8 * JDIM) = make_float2(acc[mt][j][2], acc[mt][j][3]);
        }
}

// ---------------------------------------------------------------------------
// Kernel 2: pairwise L1 + exp-sum via int8 SAD; 512 threads = (m, n-half);
// folded x-copy (half 0 only). Grid = 256 blocks (one per b).
// ---------------------------------------------------------------------------
__global__ __launch_bounds__(512) void pairwise_kernel(const float* __restrict__ x,
                                                       float* __restrict__ out) {
    __shared__ __align__(16) uint4 sQ[NB];    // 4 KB quantized rows
    __shared__ float sWmax[8];
    __shared__ float sP[NB][2];               // 2 KB partials
    const int b = blockIdx.x;
    const int tid = threadIdx.x;
    const int m = tid & 255;
    const int half = tid >> 8;
    const int lane = tid & 31;
    const int wid = tid >> 5;

    if (half == 0) {
        // folded x-copy: one float4 per thread
        {
            const int gidx = b * 256 + m;
            const int row = gidx >> 8;
            const int c = gidx & 255;
            ((float4*)(out + (size_t)row * OUT_F))[c] =
                ((const float4*)(x + (size_t)row * IN_F))[c];
        }
        // load own M row, block max, quantize, publish
        const float* rowp = g_M + (size_t)m * JDIM + b * KDIM;
        float f[16];
#pragma unroll
        for (int q = 0; q < 4; q++) {
            float4 v = ((const float4*)rowp)[q];
            f[4 * q] = v.x; f[4 * q + 1] = v.y; f[4 * q + 2] = v.z; f[4 * q + 3] = v.w;
        }
        float mx = fabsf(f[0]);
#pragma unroll
        for (int k = 1; k < 16; k++) mx = fmaxf(mx, fabsf(f[k]));
#pragma unroll
        for (int o = 16; o; o >>= 1) mx = fmaxf(mx, __shfl_xor_sync(0xFFFFFFFFu, mx, o));
        if (lane == 0) sWmax[wid] = mx;
        __syncthreads();
        float bm = sWmax[0];
#pragma unroll
        for (int w = 1; w < 8; w++) bm = fmaxf(bm, sWmax[w]);
        bm = fmaxf(bm, 1e-20f);
        const float s = 127.0f / bm;
        uint32_t q32[4];
#pragma unroll
        for (int q = 0; q < 4; q++) {
            const int q0 = __float2int_rn(f[4 * q] * s);
            const int q1 = __float2int_rn(f[4 * q + 1] * s);
            const int q2 = __float2int_rn(f[4 * q + 2] * s);
            const int q3 = __float2int_rn(f[4 * q + 3] * s);
            q32[q] = (q0 & 255) | ((q1 & 255) << 8) | ((q2 & 255) << 16) | (q3 << 24);
        }
        sQ[m] = make_uint4(q32[0], q32[1], q32[2], q32[3]);
    } else {
        __syncthreads();   // matches the reduction barrier above
    }
    __syncthreads();       // sQ published

    float bm = sWmax[0];
#pragma unroll
    for (int w = 1; w < 8; w++) bm = fmaxf(bm, sWmax[w]);
    bm = fmaxf(bm, 1e-20f);
    const float negc = -bm * (1.44269504088896f / 127.0f);

    const uint4 mq = sQ[m];
    const uint32_t myq0 = mq.x, myq1 = mq.y, myq2 = mq.z, myq3 = mq.w;

    float acc0 = 0.0f, acc1 = 0.0f;
    const int nbase = half * 128;
#pragma unroll 4
    for (int i = 0; i < 64; i++) {
        const int n = nbase + 2 * i;
        const uint4 qa = sQ[n];
        const uint4 qb = sQ[n + 1];
        int sa = vad4add(qa.x, myq0, 0);
        int sb = vad4add(qb.x, myq0, 0);
        int sa2 = vad4add(qa.y, myq1, 0);
        int sb2 = vad4add(qb.y, myq1, 0);
        sa = vad4add(qa.z, myq2, sa);
        sb = vad4add(qb.z, myq2, sb);
        sa2 = vad4add(qa.w, myq3, sa2);
        sb2 = vad4add(qb.w, myq3, sb2);
        acc0 += ex2f((float)(sa + sa2) * negc);
        acc1 += ex2f((float)(sb + sb2) * negc);
    }
    sP[m][half] = acc0 + acc1;
    __syncthreads();

    if (half == 0)
        out[(size_t)m * OUT_F + IN_F + b] = (sP[m][0] + sP[m][1]) - 1.0f;
}

extern "C" void kernel_launch(void* const* d_in, const int* in_sizes, int n_in,
                              void* d_out, int out_size) {
    const float* x = (const float*)d_in[0];   // (256, 1024)
    const float* T = (const float*)d_in[1];   // (1024, 256, 16) == W[k][n]
    float* out = (float*)d_out;               // (256, 1280)

    cudaFuncSetAttribute(gemm_kernel, cudaFuncAttributeMaxDynamicSharedMemorySize, GEMM_SMEM);
    gemm_kernel<<<dim3(JDIM / BN, NB / BM), 256, GEMM_SMEM>>>(x, T);

    pairwise_kernel<<<B_EXTRA, 512>>>(x, out);
}